// round 4
// baseline (speedup 1.0000x reference)
#include <cuda_runtime.h>

#define BATCH 2
#define NCAM  6
#define CH    128
#define IH    16
#define IW    44
#define ND    64
#define HW    (IH*IW)                 // 704
#define NPTS  (NCAM*ND*IH*IW)         // 270336 geometry points (batch-independent)
#define BEV_H 256
#define BEV_W 256
#define NBIN  (BEV_H*BEV_W)           // 65536
#define CAMSTRIDE (NCAM*ND*HW)        // depth elements per batch

// Static scratch (allocation-free per harness rules)
__device__ float g_featT[(size_t)BATCH*NCAM*HW*CH];  // feat channel-last: (bn, hw, c)
__device__ int   g_bin[NPTS];                        // bin index or -1
__device__ int   g_cnt_i[NBIN];                      // per-bin valid count
__device__ int   g_off[NBIN+1];                      // CSR offsets (exclusive)
__device__ int   g_wptr[NBIN];                       // write cursors for fill
__device__ int   g_list_fp[NPTS];                    // per-point featT pixel idx: n*HW+hw
__device__ int   g_list_dp[NPTS];                    // per-point depth idx: (n*ND+dci)*HW+hw
__device__ float g_Kinv[NCAM*9];
__device__ float g_Rm[NCAM*9];
__device__ float g_tv[NCAM*3];

// ---------------------------------------------------------------------------
// Per-camera setup (geometry identical across batch; use b=0 slices).
// ---------------------------------------------------------------------------
__global__ void setup_kernel(const float* __restrict__ intr,
                             const float* __restrict__ extr,
                             const int* __restrict__ pimg_h,
                             const int* __restrict__ pimg_w) {
    int n = threadIdx.x;
    if (n >= NCAM) return;
    float img_h = (float)pimg_h[0], img_w = (float)pimg_w[0];
    float sx = (float)IW / (img_w / 16.0f);
    float sy = (float)IH / (img_h / 16.0f);
    float rs0 = 16.0f / sx, rs1 = 16.0f / sy, rs2 = 1.0f;

    const float* Kp = intr + n*9;
    float a = Kp[0]*rs0, b = Kp[1]*rs0, c = Kp[2]*rs0;
    float d = Kp[3]*rs1, e = Kp[4]*rs1, f = Kp[5]*rs1;
    float g = Kp[6]*rs2, h = Kp[7]*rs2, i = Kp[8]*rs2;
    float A  = e*i - f*h;
    float Bc = -(d*i - f*g);
    float Cc = d*h - e*g;
    float det = a*A + b*Bc + c*Cc;
    float id = 1.0f / det;
    float* Ki = g_Kinv + n*9;
    Ki[0] = A*id;             Ki[1] = (c*h - b*i)*id;  Ki[2] = (b*f - c*e)*id;
    Ki[3] = Bc*id;            Ki[4] = (a*i - c*g)*id;  Ki[5] = (c*d - a*f)*id;
    Ki[6] = Cc*id;            Ki[7] = (b*g - a*h)*id;  Ki[8] = (a*e - b*d)*id;

    const float* Ep = extr + n*16;
    float* Rm = g_Rm + n*9;
    float* tv = g_tv + n*3;
    #pragma unroll
    for (int r = 0; r < 3; r++) {
        #pragma unroll
        for (int cc = 0; cc < 3; cc++) Rm[r*3+cc] = Ep[r*4+cc];
        tv[r] = Ep[r*4+3];
    }
}

// ---------------------------------------------------------------------------
// feat (B,N,C,H,W) -> channel-last (B,N,H,W,C): gather reads become 512B rows.
// ---------------------------------------------------------------------------
__global__ void transpose_feat(const float* __restrict__ feat) {
    int pix = blockIdx.x;            // 0 .. B*NCAM*HW-1
    int c   = threadIdx.x;           // 0 .. 127
    int hw  = pix % HW;
    int bn  = pix / HW;
    g_featT[(size_t)pix*CH + c] = feat[((size_t)bn*CH + c)*HW + hw];
}

// ---------------------------------------------------------------------------
// Geometry: one thread per point. Compute bin + validity, count per bin.
// ---------------------------------------------------------------------------
__global__ void point_kernel() {
    int wp = blockIdx.x * blockDim.x + threadIdx.x;
    if (wp >= NPTS) return;

    int w   = wp % IW;  int t = wp / IW;
    int h   = t % IH;   t /= IH;
    int dci = t % ND;
    int n   = t / ND;

    float dd = 1.0f + (59.0f / 63.0f) * (float)dci;  // linspace(1,60,64)
    float ux = (float)w * dd;
    float vy = (float)h * dd;

    const float* Ki = g_Kinv + n*9;
    float pcx = Ki[0]*ux + Ki[1]*vy + Ki[2]*dd;
    float pcy = Ki[3]*ux + Ki[4]*vy + Ki[5]*dd;
    float pcz = Ki[6]*ux + Ki[7]*vy + Ki[8]*dd;

    const float* Rm = g_Rm + n*9;
    const float* tv = g_tv + n*3;
    float px = Rm[0]*pcx + Rm[1]*pcy + Rm[2]*pcz + tv[0];
    float py = Rm[3]*pcx + Rm[4]*pcy + Rm[5]*pcz + tv[1];
    float pz = Rm[6]*pcx + Rm[7]*pcy + Rm[8]*pcz + tv[2];

    int xi = (int)__fdiv_rn(px - (-51.2f), 0.4f);
    int yi = (int)__fdiv_rn(py - (-51.2f), 0.4f);
    bool valid = (xi >= 0) & (xi < BEV_W) & (yi >= 0) & (yi < BEV_H)
               & (pz >= -5.0f) & (pz <= 3.0f);

    int bin = yi * BEV_W + xi;
    g_bin[wp] = valid ? bin : -1;
    if (valid) atomicAdd(&g_cnt_i[bin], 1);
}

// ---------------------------------------------------------------------------
// Single-block exclusive scan of 65536 counts -> CSR offsets + write cursors.
// 1024 threads x 64 bins each; Hillis-Steele over the 1024 partials.
// ---------------------------------------------------------------------------
__global__ void scan_kernel() {
    __shared__ int sp[1024];
    int t = threadIdx.x;
    int base = t * 64;
    int s = 0;
    #pragma unroll 8
    for (int j = 0; j < 64; j++) s += g_cnt_i[base + j];
    sp[t] = s;
    __syncthreads();
    #pragma unroll
    for (int d = 1; d < 1024; d <<= 1) {
        int v = (t >= d) ? sp[t - d] : 0;
        __syncthreads();
        sp[t] += v;
        __syncthreads();
    }
    int run = sp[t] - s;   // exclusive prefix for this thread's range
    for (int j = 0; j < 64; j++) {
        g_off[base + j]  = run;
        g_wptr[base + j] = run;
        run += g_cnt_i[base + j];
    }
    if (t == 1023) g_off[NBIN] = run;
}

// ---------------------------------------------------------------------------
// Fill: compact valid points into per-bin lists with precomputed offsets.
// ---------------------------------------------------------------------------
__global__ void fill_kernel() {
    int wp = blockIdx.x * blockDim.x + threadIdx.x;
    if (wp >= NPTS) return;
    int bin = g_bin[wp];
    if (bin < 0) return;

    int w   = wp % IW;  int t = wp / IW;
    int h   = t % IH;   t /= IH;
    int dci = t % ND;
    int n   = t / ND;
    int hw  = h * IW + w;

    int pos = atomicAdd(&g_wptr[bin], 1);
    g_list_fp[pos] = n * HW + hw;
    g_list_dp[pos] = (n * ND + dci) * HW + hw;
}

// ---------------------------------------------------------------------------
// Gather: block = 32-bin tile (one BEV row segment), 8 warps; warp owns bins
// stride-8. Registers accumulate feat4*depth for both batches; smem stages
// the (bin,c) -> (c,bin) transpose fused with /(K+1e-5); coalesced STG.
// ---------------------------------------------------------------------------
__global__ void __launch_bounds__(256) gather_kernel(const float* __restrict__ depth,
                                                     float* __restrict__ out) {
    __shared__ float smem[BATCH][32][CH + 1];   // pad 129: conflict-free phase-2 reads
    __shared__ float scnt[32];
    int bin0 = blockIdx.x * 32;
    int warp = threadIdx.x >> 5;
    int lane = threadIdx.x & 31;

    for (int bl = warp; bl < 32; bl += 8) {
        int bin = bin0 + bl;
        int beg = g_off[bin];
        int end = g_off[bin + 1];
        float4 a0 = {0.f, 0.f, 0.f, 0.f};
        float4 a1 = {0.f, 0.f, 0.f, 0.f};
        for (int i = beg; i < end; i++) {
            int fpix = g_list_fp[i];
            int dpo  = g_list_dp[i];
            float d0 = __ldg(&depth[dpo]);
            float d1 = __ldg(&depth[CAMSTRIDE + dpo]);
            float4 v0 = *((const float4*)(g_featT + (size_t)fpix * CH) + lane);
            float4 v1 = *((const float4*)(g_featT + ((size_t)(NCAM*HW) + fpix) * CH) + lane);
            a0.x += v0.x * d0;  a0.y += v0.y * d0;  a0.z += v0.z * d0;  a0.w += v0.w * d0;
            a1.x += v1.x * d1;  a1.y += v1.y * d1;  a1.z += v1.z * d1;  a1.w += v1.w * d1;
        }
        int c4 = lane * 4;
        smem[0][bl][c4+0] = a0.x;  smem[0][bl][c4+1] = a0.y;
        smem[0][bl][c4+2] = a0.z;  smem[0][bl][c4+3] = a0.w;
        smem[1][bl][c4+0] = a1.x;  smem[1][bl][c4+1] = a1.y;
        smem[1][bl][c4+2] = a1.z;  smem[1][bl][c4+3] = a1.w;
        if (lane == 0) scnt[bl] = (float)(end - beg);
    }
    __syncthreads();

    // 256 output rows (b,c), each 32 consecutive bins -> coalesced 128B stores
    #pragma unroll
    for (int r = warp; r < BATCH * CH; r += 8) {
        int b = r >> 7;
        int c = r & 127;
        float v   = smem[b][lane][c];            // addr = lane*129 + c: conflict-free
        float cnt = scnt[lane] + 1e-5f;
        out[((size_t)(b * CH + c)) * NBIN + bin0 + lane] = __fdiv_rn(v, cnt);
    }
}

extern "C" void kernel_launch(void* const* d_in, const int* in_sizes, int n_in,
                              void* d_out, int out_size) {
    const float* feat  = (const float*)d_in[0];
    const float* depth = (const float*)d_in[1];
    const float* intr  = (const float*)d_in[2];
    const float* extr  = (const float*)d_in[3];
    const int*   img_h = (const int*)d_in[4];
    const int*   img_w = (const int*)d_in[5];
    float* out = (float*)d_out;

    void* cnt_ptr;
    cudaGetSymbolAddress(&cnt_ptr, g_cnt_i);
    cudaMemsetAsync(cnt_ptr, 0, sizeof(int) * NBIN);

    setup_kernel<<<1, 32>>>(intr, extr, img_h, img_w);
    transpose_feat<<<BATCH*NCAM*HW, CH>>>(feat);
    point_kernel<<<(NPTS + 255)/256, 256>>>();
    scan_kernel<<<1, 1024>>>();
    fill_kernel<<<(NPTS + 255)/256, 256>>>();
    gather_kernel<<<NBIN/32, 256>>>(depth, out);
}

// round 5
// speedup vs baseline: 3.5427x; 3.5427x over previous
#include <cuda_runtime.h>

#define BATCH 2
#define NCAM  6
#define CH    128
#define IH    16
#define IW    44
#define ND    64
#define HW    (IH*IW)                 // 704
#define NPTS  (NCAM*ND*IH*IW)         // 270336 geometry points (batch-independent)
#define BEV_H 256
#define BEV_W 256
#define NBIN  (BEV_H*BEV_W)           // 65536
#define NTILE (NBIN/32)               // 2048
#define CAMSTRIDE (NCAM*ND*HW)        // depth elements per batch

// Static scratch (allocation-free per harness rules)
__device__ float g_featT[(size_t)BATCH*NCAM*HW*CH];  // feat channel-last: (bn, hw, c)
__device__ int   g_bin[NPTS];                        // bin index or -1
__device__ __align__(16) int g_cnt_i[NBIN];          // per-bin valid count
__device__ __align__(16) int g_off[NBIN+1];          // CSR offsets (exclusive)
__device__ __align__(16) int g_wptr[NBIN];           // write cursors for fill
__device__ int   g_bsum[64];                         // per-scan-block sums
__device__ int   g_boff[64];                         // scanned block offsets
__device__ int   g_sched[NTILE];                     // tile schedule, hot first
__device__ int   g_list_fp[NPTS];                    // per-point featT pixel idx: n*HW+hw
__device__ int   g_list_dp[NPTS];                    // per-point depth idx: (n*ND+dci)*HW+hw
__device__ float g_Kinv[NCAM*9];
__device__ float g_Rm[NCAM*9];
__device__ float g_tv[NCAM*3];

// ---------------------------------------------------------------------------
// Per-camera setup (geometry identical across batch; use b=0 slices).
// ---------------------------------------------------------------------------
__global__ void setup_kernel(const float* __restrict__ intr,
                             const float* __restrict__ extr,
                             const int* __restrict__ pimg_h,
                             const int* __restrict__ pimg_w) {
    int n = threadIdx.x;
    if (n >= NCAM) return;
    float img_h = (float)pimg_h[0], img_w = (float)pimg_w[0];
    float sx = (float)IW / (img_w / 16.0f);
    float sy = (float)IH / (img_h / 16.0f);
    float rs0 = 16.0f / sx, rs1 = 16.0f / sy, rs2 = 1.0f;

    const float* Kp = intr + n*9;
    float a = Kp[0]*rs0, b = Kp[1]*rs0, c = Kp[2]*rs0;
    float d = Kp[3]*rs1, e = Kp[4]*rs1, f = Kp[5]*rs1;
    float g = Kp[6]*rs2, h = Kp[7]*rs2, i = Kp[8]*rs2;
    float A  = e*i - f*h;
    float Bc = -(d*i - f*g);
    float Cc = d*h - e*g;
    float det = a*A + b*Bc + c*Cc;
    float id = 1.0f / det;
    float* Ki = g_Kinv + n*9;
    Ki[0] = A*id;             Ki[1] = (c*h - b*i)*id;  Ki[2] = (b*f - c*e)*id;
    Ki[3] = Bc*id;            Ki[4] = (a*i - c*g)*id;  Ki[5] = (c*d - a*f)*id;
    Ki[6] = Cc*id;            Ki[7] = (b*g - a*h)*id;  Ki[8] = (a*e - b*d)*id;

    const float* Ep = extr + n*16;
    float* Rm = g_Rm + n*9;
    float* tv = g_tv + n*3;
    #pragma unroll
    for (int r = 0; r < 3; r++) {
        #pragma unroll
        for (int cc = 0; cc < 3; cc++) Rm[r*3+cc] = Ep[r*4+cc];
        tv[r] = Ep[r*4+3];
    }
}

// ---------------------------------------------------------------------------
// feat (B,N,C,H,W) -> channel-last (B,N,H,W,C) via 32x32 smem tiles:
// both the global read (along hw) and write (along c) are coalesced.
// grid (CH/32, HW/32, B*N), block (32, 8).
// ---------------------------------------------------------------------------
__global__ void transpose_feat(const float* __restrict__ feat) {
    __shared__ float tile[32][33];
    int c0  = blockIdx.x * 32;
    int hw0 = blockIdx.y * 32;
    int bn  = blockIdx.z;
    int x = threadIdx.x, y = threadIdx.y;
    const float* src = feat + (size_t)bn * CH * HW;
    #pragma unroll
    for (int k = 0; k < 4; k++) {
        int c = c0 + y + k*8;
        tile[y + k*8][x] = src[(size_t)c * HW + hw0 + x];
    }
    __syncthreads();
    #pragma unroll
    for (int k = 0; k < 4; k++) {
        int hw = hw0 + y + k*8;
        g_featT[((size_t)bn * HW + hw) * CH + c0 + x] = tile[x][y + k*8];
    }
}

// ---------------------------------------------------------------------------
// Geometry: one thread per point. Compute bin + validity, count per bin.
// ---------------------------------------------------------------------------
__global__ void point_kernel() {
    int wp = blockIdx.x * blockDim.x + threadIdx.x;
    if (wp >= NPTS) return;

    int w   = wp % IW;  int t = wp / IW;
    int h   = t % IH;   t /= IH;
    int dci = t % ND;
    int n   = t / ND;

    float dd = 1.0f + (59.0f / 63.0f) * (float)dci;  // linspace(1,60,64)
    float ux = (float)w * dd;
    float vy = (float)h * dd;

    const float* Ki = g_Kinv + n*9;
    float pcx = Ki[0]*ux + Ki[1]*vy + Ki[2]*dd;
    float pcy = Ki[3]*ux + Ki[4]*vy + Ki[5]*dd;
    float pcz = Ki[6]*ux + Ki[7]*vy + Ki[8]*dd;

    const float* Rm = g_Rm + n*9;
    const float* tv = g_tv + n*3;
    float px = Rm[0]*pcx + Rm[1]*pcy + Rm[2]*pcz + tv[0];
    float py = Rm[3]*pcx + Rm[4]*pcy + Rm[5]*pcz + tv[1];
    float pz = Rm[6]*pcx + Rm[7]*pcy + Rm[8]*pcz + tv[2];

    int xi = (int)__fdiv_rn(px - (-51.2f), 0.4f);
    int yi = (int)__fdiv_rn(py - (-51.2f), 0.4f);
    bool valid = (xi >= 0) & (xi < BEV_W) & (yi >= 0) & (yi < BEV_H)
               & (pz >= -5.0f) & (pz <= 3.0f);

    int bin = yi * BEV_W + xi;
    g_bin[wp] = valid ? bin : -1;
    if (valid) atomicAdd(&g_cnt_i[bin], 1);
}

// ---------------------------------------------------------------------------
// Parallel scan, stage 1: 64 blocks x 256 threads, 4 bins/thread (int4).
// Coalesced loads, warp-shuffle block scan, local-exclusive prefixes to g_off.
// ---------------------------------------------------------------------------
__global__ void scan1_kernel() {
    __shared__ int wsum[8];
    __shared__ int wexcl[8];
    int t  = threadIdx.x;
    int gb = blockIdx.x * 1024 + t * 4;
    int4 c = *(const int4*)&g_cnt_i[gb];
    int s = c.x + c.y + c.z + c.w;
    int lane = t & 31, wid = t >> 5;
    int incl = s;
    #pragma unroll
    for (int d = 1; d < 32; d <<= 1) {
        int v = __shfl_up_sync(0xffffffffu, incl, d);
        if (lane >= d) incl += v;
    }
    if (lane == 31) wsum[wid] = incl;
    __syncthreads();
    if (t < 8) {
        int v = wsum[t];
        int iv = v;
        #pragma unroll
        for (int d = 1; d < 8; d <<= 1) {
            int u = __shfl_up_sync(0xffu, iv, d);
            if (t >= d) iv += u;
        }
        wexcl[t] = iv - v;
    }
    __syncthreads();
    int excl = incl - s + wexcl[wid];
    int4 o;
    o.x = excl; o.y = o.x + c.x; o.z = o.y + c.y; o.w = o.z + c.z;
    *(int4*)&g_off[gb] = o;
    if (t == 255) g_bsum[blockIdx.x] = excl + s;
}

// Stage 2: scan the 64 block sums (1 block, 64 threads), write grand total.
__global__ void scan2_kernel() {
    __shared__ int w0;
    int t = threadIdx.x;                 // 0..63
    int v = g_bsum[t];
    int lane = t & 31, wid = t >> 5;
    int iv = v;
    #pragma unroll
    for (int d = 1; d < 32; d <<= 1) {
        int u = __shfl_up_sync(0xffffffffu, iv, d);
        if (lane >= d) iv += u;
    }
    if (t == 31) w0 = iv;
    __syncthreads();
    int excl = iv - v + (wid ? w0 : 0);
    g_boff[t] = excl;
    if (t == 63) g_off[NBIN] = excl + v;
}

// Stage 3: add block offsets; also materialize write cursors.
__global__ void scan3_kernel() {
    int t  = threadIdx.x;
    int gb = blockIdx.x * 1024 + t * 4;
    int base = g_boff[blockIdx.x];
    int4 o = *(const int4*)&g_off[gb];
    o.x += base; o.y += base; o.z += base; o.w += base;
    *(int4*)&g_off[gb]  = o;
    *(int4*)&g_wptr[gb] = o;
}

// ---------------------------------------------------------------------------
// Tile schedule: bucket 2048 tiles by point count (hot first) so the gather's
// longest-running blocks start in wave 1. Single block, 1024 threads.
// ---------------------------------------------------------------------------
__global__ void sched_kernel() {
    __shared__ int bcnt[8], bbase[8];
    int t = threadIdx.x;
    if (t < 8) bcnt[t] = 0;
    __syncthreads();
    int ks[2];
    #pragma unroll
    for (int j = 0; j < 2; j++) {
        int tile = t + j * 1024;
        int cnt = g_off[tile*32 + 32] - g_off[tile*32];
        int k = cnt > 4096 ? 0 : cnt > 2048 ? 1 : cnt > 1024 ? 2 : cnt > 512 ? 3 :
                cnt > 256  ? 4 : cnt > 128  ? 5 : cnt > 64   ? 6 : 7;
        ks[j] = k;
        atomicAdd(&bcnt[k], 1);
    }
    __syncthreads();
    if (t == 0) {
        int r = 0;
        #pragma unroll
        for (int k = 0; k < 8; k++) { bbase[k] = r; r += bcnt[k]; }
    }
    __syncthreads();
    #pragma unroll
    for (int j = 0; j < 2; j++) {
        int pos = atomicAdd(&bbase[ks[j]], 1);
        g_sched[pos] = t + j * 1024;
    }
}

// ---------------------------------------------------------------------------
// Fill: compact valid points into per-bin lists with precomputed offsets.
// ---------------------------------------------------------------------------
__global__ void fill_kernel() {
    int wp = blockIdx.x * blockDim.x + threadIdx.x;
    if (wp >= NPTS) return;
    int bin = g_bin[wp];
    if (bin < 0) return;

    int w   = wp % IW;  int t = wp / IW;
    int h   = t % IH;   t /= IH;
    int dci = t % ND;
    int n   = t / ND;
    int hw  = h * IW + w;

    int pos = atomicAdd(&g_wptr[bin], 1);
    g_list_fp[pos] = n * HW + hw;
    g_list_dp[pos] = (n * ND + dci) * HW + hw;
}

// ---------------------------------------------------------------------------
// Gather: block = 32-bin tile taken from the hot-first schedule; 16 warps,
// warp owns 2 bins (stride 16). Registers accumulate feat4*depth for both
// batches; smem stages the (bin,c)->(c,bin) transpose fused with /(K+1e-5).
// ---------------------------------------------------------------------------
__global__ void __launch_bounds__(512) gather_kernel(const float* __restrict__ depth,
                                                     float* __restrict__ out) {
    __shared__ float smem[BATCH][32][CH + 1];
    __shared__ float scnt[32];
    int tile = g_sched[blockIdx.x];
    int bin0 = tile * 32;
    int warp = threadIdx.x >> 5;
    int lane = threadIdx.x & 31;

    for (int bl = warp; bl < 32; bl += 16) {
        int bin = bin0 + bl;
        int beg = g_off[bin];
        int end = g_off[bin + 1];
        float4 a0 = {0.f, 0.f, 0.f, 0.f};
        float4 a1 = {0.f, 0.f, 0.f, 0.f};
        #pragma unroll 4
        for (int i = beg; i < end; i++) {
            int fpix = g_list_fp[i];
            int dpo  = g_list_dp[i];
            float d0 = __ldg(&depth[dpo]);
            float d1 = __ldg(&depth[CAMSTRIDE + dpo]);
            float4 v0 = *((const float4*)(g_featT + (size_t)fpix * CH) + lane);
            float4 v1 = *((const float4*)(g_featT + ((size_t)(NCAM*HW) + fpix) * CH) + lane);
            a0.x += v0.x * d0;  a0.y += v0.y * d0;  a0.z += v0.z * d0;  a0.w += v0.w * d0;
            a1.x += v1.x * d1;  a1.y += v1.y * d1;  a1.z += v1.z * d1;  a1.w += v1.w * d1;
        }
        int c4 = lane * 4;
        smem[0][bl][c4+0] = a0.x;  smem[0][bl][c4+1] = a0.y;
        smem[0][bl][c4+2] = a0.z;  smem[0][bl][c4+3] = a0.w;
        smem[1][bl][c4+0] = a1.x;  smem[1][bl][c4+1] = a1.y;
        smem[1][bl][c4+2] = a1.z;  smem[1][bl][c4+3] = a1.w;
        if (lane == 0) scnt[bl] = (float)(end - beg);
    }
    __syncthreads();

    // 256 output rows (b,c), each 32 consecutive bins -> coalesced 128B stores
    for (int r = warp; r < BATCH * CH; r += 16) {
        int b = r >> 7;
        int c = r & 127;
        float v   = smem[b][lane][c];            // stride-129: conflict-free
        float cnt = scnt[lane] + 1e-5f;
        out[((size_t)(b * CH + c)) * NBIN + bin0 + lane] = __fdiv_rn(v, cnt);
    }
}

extern "C" void kernel_launch(void* const* d_in, const int* in_sizes, int n_in,
                              void* d_out, int out_size) {
    const float* feat  = (const float*)d_in[0];
    const float* depth = (const float*)d_in[1];
    const float* intr  = (const float*)d_in[2];
    const float* extr  = (const float*)d_in[3];
    const int*   img_h = (const int*)d_in[4];
    const int*   img_w = (const int*)d_in[5];
    float* out = (float*)d_out;

    void* cnt_ptr;
    cudaGetSymbolAddress(&cnt_ptr, g_cnt_i);
    cudaMemsetAsync(cnt_ptr, 0, sizeof(int) * NBIN);

    setup_kernel<<<1, 32>>>(intr, extr, img_h, img_w);
    transpose_feat<<<dim3(CH/32, HW/32, BATCH*NCAM), dim3(32, 8)>>>(feat);
    point_kernel<<<(NPTS + 255)/256, 256>>>();
    scan1_kernel<<<64, 256>>>();
    scan2_kernel<<<1, 64>>>();
    scan3_kernel<<<64, 256>>>();
    sched_kernel<<<1, 1024>>>();
    fill_kernel<<<(NPTS + 255)/256, 256>>>();
    gather_kernel<<<NTILE, 512>>>(depth, out);
}